// round 5
// baseline (speedup 1.0000x reference)
#include <cuda_runtime.h>
#include <math.h>

#define K 128
#define E 4096
#define M 512
#define NUM_UPDATE 3
#define THRESHOLD 0.05f
#define HOT 8
#define MAXNZ 32
#define NBLK 4            // e-chunks in big grid
#define EPB 1024          // e per block (4 per thread, 256 threads)

// ---------------- device scratch ----------------
__device__ __align__(16) unsigned char g_nzpk[E * MAXNZ];
__device__ unsigned char g_cnt[E];
__device__ float2 g_icbz[E];                  // (Ic, beta2*Zc) per e
__device__ float  g_bz[E];
__device__ float2 g_buw[(size_t)K * E];       // (beta1, user*W)
__device__ float  g_Bc[(size_t)K * E * HOT];  // gathered B, diag/pad zeroed
__device__ __align__(16) float g_dval[E * HOT]; // dv[j_i(e)] per step
__device__ float  g_dv[K];
__device__ float  g_u[K];
__device__ int    g_upd[K];
__device__ float  g_partial[K * NBLK];
__device__ unsigned g_done[NUM_UPDATE];

__device__ __forceinline__ float sigm_neg(float x) {
    return __fdividef(1.0f, 1.0f + __expf(x));  // sigmoid(-x)
}

// ---------------- init0: nz lists, dval0, Ic0, bz, u0 ----------------
__global__ void init0_kernel(const float* __restrict__ q_kn,
                             const float* __restrict__ U,
                             const int* __restrict__ stu_id,
                             const int* __restrict__ kn_id,
                             const float* __restrict__ gamma_c,
                             const float* __restrict__ dd,
                             const float* __restrict__ score,
                             const float* __restrict__ beta2,
                             const float* __restrict__ gs,
                             const float* __restrict__ A_emb) {
    int tid = threadIdx.x;
    int w = tid >> 5, l = tid & 31;
    int e = blockIdx.x * 8 + w;
    int stu = stu_id[0];

    if (l < HOT) g_dval[e * HOT + l] = 0.0f;
    __syncwarp();

    int base = 0;
    float su = 0.0f;
#pragma unroll
    for (int r = 0; r < 4; r++) {
        int j = r * 32 + l;
        float q = q_kn[(size_t)e * K + j];
        unsigned m = __ballot_sync(0xFFFFFFFFu, q != 0.0f);
        if (q != 0.0f) {
            int pos = base + __popc(m & ((1u << l) - 1u));
            float u0j = U[(size_t)stu * K + j];
            if (pos < MAXNZ) g_nzpk[e * MAXNZ + pos] = (unsigned char)j;
            float dvj = u0j - 0.5f;
            dvj = (fabsf(dvj) > THRESHOLD) ? dvj : 0.0f;
            if (pos < HOT) g_dval[e * HOT + pos] = dvj;
            su += u0j;
        }
        base += __popc(m);
    }
    su += __shfl_xor_sync(0xFFFFFFFFu, su, 16);
    su += __shfl_xor_sync(0xFFFFFFFFu, su, 8);
    su += __shfl_xor_sync(0xFFFFFFFFu, su, 4);
    su += __shfl_xor_sync(0xFFFFFFFFu, su, 2);
    su += __shfl_xor_sync(0xFFFFFFFFu, su, 1);
    if (l == 0) {
        g_cnt[e] = (unsigned char)(base < MAXNZ ? base : MAXNZ);
        float x  = (gamma_c[e] / dd[e]) * (score[e] - 0.5f);
        float bz = beta2[e] * (sigm_neg(x) - 0.5f);
        g_bz[e] = bz;
        float t  = score[e] - su / dd[e];
        float yc = __expf(-t * t);
        float ic = A_emb[3 * e + 0] * (1.0f - gs[2 * e + 0])
                 + A_emb[3 * e + 1] * (1.0f - gs[2 * e + 1])
                 + A_emb[3 * e + 2] * yc;
        g_icbz[e] = make_float2(sigm_neg(ic), bz);
    }

    if (blockIdx.x == 0) {
        if (tid < NUM_UPDATE) g_done[tid] = 0u;
        if (tid < K) {
            float u0 = U[(size_t)stu * K + tid];
            g_u[tid] = u0;
            float dv = u0 - 0.5f;
            g_dv[tid] = (fabsf(dv) > THRESHOLD) ? dv : 0.0f;
            g_upd[tid] = 0;
        }
        __syncthreads();
        if (tid < K) {
            int kn = kn_id[tid];
            if (kn >= 0 && kn < K) g_upd[kn] = 1;
        }
    }
}

// ---------------- init0b: buw = (beta1, user*W), vectorized ----------------
__global__ void init0b_kernel(const float* __restrict__ beta1,
                              const float* __restrict__ W,
                              const float* __restrict__ user) {
    int i4 = blockIdx.x * blockDim.x + threadIdx.x;   // float4 index
    const int N4 = K * E / 4;
    for (; i4 < N4; i4 += gridDim.x * blockDim.x) {
        float4 b = ((const float4*)beta1)[i4];
        float4 w = ((const float4*)W)[i4];
        float4 u = ((const float4*)user)[i4];
        float2* dst = g_buw + i4 * 4;
        dst[0] = make_float2(b.x, u.x * w.x);
        dst[1] = make_float2(b.y, u.y * w.y);
        dst[2] = make_float2(b.z, u.z * w.z);
        dst[3] = make_float2(b.w, u.w * w.w);
    }
}

// ---------------- init1: build Bc (one-time scattered gather, batched) ----------------
__global__ __launch_bounds__(256, 2) void init1_kernel(const float* __restrict__ Bm) {
    int k = blockIdx.y;
    size_t kE = (size_t)k * E;
    int tid = threadIdx.x;
    int e0 = blockIdx.x * EPB + tid;

    // phase 1: batch index loads
    uint2 pk[4]; int cnt[4];
#pragma unroll
    for (int r = 0; r < 4; r++) {
        int e = e0 + r * 256;
        pk[r]  = *(const uint2*)(g_nzpk + e * MAXNZ);
        cnt[r] = g_cnt[e];
    }
    // phase 2: batch all 32 (predicated) gathers
    float v[4][HOT];
#pragma unroll
    for (int r = 0; r < 4; r++) {
        int e = e0 + r * 256;
        const float* __restrict__ Brow = Bm + (kE + e) * K;
        unsigned pw0 = pk[r].x, pw1 = pk[r].y;
#pragma unroll
        for (int i = 0; i < HOT; i++) {
            int j = ((i < 4 ? pw0 : pw1) >> ((i & 3) * 8)) & 0xFF;
            v[r][i] = (i < cnt[r] && j != k) ? __ldg(Brow + j) : 0.0f;
        }
    }
    // phase 3: store
#pragma unroll
    for (int r = 0; r < 4; r++) {
        int e = e0 + r * 256;
        float4* dst = (float4*)(g_Bc + (kE + e) * HOT);
        dst[0] = make_float4(v[r][0], v[r][1], v[r][2], v[r][3]);
        dst[1] = make_float4(v[r][4], v[r][5], v[r][6], v[r][7]);
    }
}

// ---------------- big step kernel (load-batched, fused epilogue) ----------------
__global__ __launch_bounds__(256, 2) void big_kernel(const float* __restrict__ Bm,
                                                     const float* __restrict__ dd,
                                                     const float* __restrict__ score,
                                                     const float* __restrict__ gs,
                                                     const float* __restrict__ A_emb,
                                                     float* __restrict__ out,
                                                     int step) {
    int k = blockIdx.y;
    size_t kE = (size_t)k * E;
    int tid = threadIdx.x;
    int e0 = blockIdx.x * EPB + tid;

    // ---- phase 1: batch ALL loads ----
    float4 b0[4], b1[4], d0[4], d1[4];
    float2 icz[4], bw[4];
    int cnt[4];
#pragma unroll
    for (int r = 0; r < 4; r++) {
        int e = e0 + r * 256;
        const float4* bc = (const float4*)(g_Bc + (kE + e) * HOT);
        const float4* dp = (const float4*)(g_dval + e * HOT);
        b0[r] = bc[0];  b1[r] = bc[1];
        d0[r] = dp[0];  d1[r] = dp[1];
        cnt[r] = g_cnt[e];
        icz[r] = g_icbz[e];
        bw[r]  = g_buw[kE + e];
    }

    // ---- phase 2: hot dots ----
    float dot[4];
#pragma unroll
    for (int r = 0; r < 4; r++) {
        dot[r] = b0[r].x * d0[r].x + b0[r].y * d0[r].y + b0[r].z * d0[r].z + b0[r].w * d0[r].w
               + b1[r].x * d1[r].x + b1[r].y * d1[r].y + b1[r].z * d1[r].z + b1[r].w * d1[r].w;
    }

    // ---- phase 3: rare tails (off the main path) ----
    if ((cnt[0] | cnt[1] | cnt[2] | cnt[3]) > HOT) {
#pragma unroll
        for (int r = 0; r < 4; r++) {
            if (cnt[r] > HOT) {
                int e = e0 + r * 256;
                const uint4* pkp = (const uint4*)(g_nzpk + e * MAXNZ);
                uint4 p0 = pkp[0], p1 = pkp[1];
                unsigned pw[8] = {p0.x, p0.y, p0.z, p0.w, p1.x, p1.y, p1.z, p1.w};
                const float* __restrict__ Brow = Bm + (kE + e) * K;
                for (int i = HOT; i < cnt[r]; i++) {
                    int j = (pw[i >> 2] >> ((i & 3) * 8)) & 0xFF;
                    if (j != k) dot[r] += __ldg(Brow + j) * g_dv[j];
                }
            }
        }
    }

    // ---- phase 4: nonlinearity + accumulate ----
    float acc = 0.0f;
#pragma unroll
    for (int r = 0; r < 4; r++) {
        float gkc = sigm_neg(dot[r]) - 1.0f;
        float wk  = icz[r].x * (bw[r].x * gkc + icz[r].y);
        acc += bw[r].y * wk;
    }

    // deterministic block reduction
    __shared__ float warpacc[8];
    int w = tid >> 5, l = tid & 31;
    acc += __shfl_xor_sync(0xFFFFFFFFu, acc, 16);
    acc += __shfl_xor_sync(0xFFFFFFFFu, acc, 8);
    acc += __shfl_xor_sync(0xFFFFFFFFu, acc, 4);
    acc += __shfl_xor_sync(0xFFFFFFFFu, acc, 2);
    acc += __shfl_xor_sync(0xFFFFFFFFu, acc, 1);
    if (l == 0) warpacc[w] = acc;
    __syncthreads();

    __shared__ bool is_last;
    if (tid == 0) {
        float s = 0.0f;
#pragma unroll
        for (int i = 0; i < 8; i++) s += warpacc[i];
        g_partial[k * NBLK + blockIdx.x] = s;
        __threadfence();
        unsigned t = atomicAdd(&g_done[step], 1u);
        is_last = (t == (unsigned)(NBLK * K - 1));
    }
    __syncthreads();
    if (!is_last) return;
    __threadfence();

    // ---- fused epilogue (one block) ----
    __shared__ float s_un[K];
    __shared__ float s_dvn[K];
    __shared__ float red[K];
    if (tid < K) {
        float s = 0.0f;
#pragma unroll
        for (int c = 0; c < NBLK; c++) s += g_partial[tid * NBLK + c];
        float u_old = g_u[tid];
        float u_new = sigm_neg(s);
        float un = g_upd[tid] ? u_new : u_old;
        float ddf = un - u_old;
        red[tid] = ddf * ddf;
        s_un[tid] = un;
        float dvn = un - 0.5f;
        dvn = (fabsf(dvn) > THRESHOLD) ? dvn : 0.0f;
        s_dvn[tid] = dvn;
        g_u[tid] = un;
        g_dv[tid] = dvn;
        if (step == NUM_UPDATE - 2) out[K + tid] = un;  // state_2nd_last
        if (step == NUM_UPDATE - 1) out[tid]     = un;  // state_last
    }
    __syncthreads();
#pragma unroll
    for (int off = 64; off > 0; off >>= 1) {
        if (tid < off && tid + off < K) red[tid] += red[tid + off];
        __syncthreads();
    }
    if (tid == 0) out[2 * K + M + step] = sqrtf(red[0]);

    if (step < NUM_UPDATE - 1) {
        // prepare next-step inputs (dval, Ic); pk loads are affine -> pipelined
#pragma unroll 4
        for (int i = 0; i < E / 256; i++) {
            int e = i * 256 + tid;
            const uint4* pkp = (const uint4*)(g_nzpk + e * MAXNZ);
            uint4 p0 = pkp[0], p1 = pkp[1];
            unsigned pw[8] = {p0.x, p0.y, p0.z, p0.w, p1.x, p1.y, p1.z, p1.w};
            int cnte = g_cnt[e];
            float su = 0.0f;
            float v[HOT];
#pragma unroll
            for (int idx = 0; idx < HOT; idx++) {
                int j = (pw[idx >> 2] >> ((idx & 3) * 8)) & 0xFF;
                bool valid = idx < cnte;
                v[idx] = valid ? s_dvn[j] : 0.0f;
                su += valid ? s_un[j] : 0.0f;
            }
            for (int idx = HOT; idx < cnte; idx++) {
                int j = (pw[idx >> 2] >> ((idx & 3) * 8)) & 0xFF;
                su += s_un[j];
            }
            float4* dst = (float4*)(g_dval + e * HOT);
            dst[0] = make_float4(v[0], v[1], v[2], v[3]);
            dst[1] = make_float4(v[4], v[5], v[6], v[7]);
            float t  = score[e] - su / dd[e];
            float yc = __expf(-t * t);
            float ic = A_emb[3 * e + 0] * (1.0f - gs[2 * e + 0])
                     + A_emb[3 * e + 1] * (1.0f - gs[2 * e + 1])
                     + A_emb[3 * e + 2] * yc;
            g_icbz[e] = make_float2(sigm_neg(ic), g_bz[e]);
        }
    }
}

// ---------------- final predict ----------------
__global__ void predict_kernel(const float* __restrict__ dd,
                               const float* __restrict__ alpha,
                               const float* __restrict__ gamma_e,
                               const int* __restrict__ ex_id,
                               float* __restrict__ out) {
    __shared__ float s_u[K];
    int tid = threadIdx.x;
    if (tid < K) s_u[tid] = g_u[tid];
    __syncthreads();

    int m = blockIdx.x * 256 + tid;
    if (m < M) {
        int e = ex_id[m];
        const uint4* pkp = (const uint4*)(g_nzpk + e * MAXNZ);
        uint4 p0 = pkp[0], p1 = pkp[1];
        unsigned pw[8] = {p0.x, p0.y, p0.z, p0.w, p1.x, p1.y, p1.z, p1.w};
        int cnt = g_cnt[e];
        float accv = 0.0f;
        for (int i = 0; i < cnt; i++) {
            int j = (pw[i >> 2] >> ((i & 3) * 8)) & 0xFF;
            accv += s_u[j];
        }
        float Ukse = accv / dd[e] - 0.5f;
        out[2 * K + m] = sigm_neg(alpha[e] * Ukse + gamma_e[e]);
    }
}

// ---------------- launch ----------------
extern "C" void kernel_launch(void* const* d_in, const int* in_sizes, int n_in,
                              void* d_out, int out_size) {
    const float* U       = (const float*)d_in[0];
    const float* W       = (const float*)d_in[1];
    const float* beta1   = (const float*)d_in[2];
    const float* beta2   = (const float*)d_in[3];
    const float* Bm      = (const float*)d_in[4];
    const float* gs      = (const float*)d_in[5];
    const float* A_emb   = (const float*)d_in[6];
    const float* gamma_c = (const float*)d_in[7];
    const float* gamma_e = (const float*)d_in[8];
    const float* alpha   = (const float*)d_in[9];
    const float* score   = (const float*)d_in[10];
    const float* user    = (const float*)d_in[11];
    const float* q_kn    = (const float*)d_in[12];
    const float* d       = (const float*)d_in[13];
    const int*   stu_id  = (const int*)d_in[14];
    const int*   kn_id   = (const int*)d_in[15];
    const int*   ex_id   = (const int*)d_in[16];
    float* out = (float*)d_out;

    init0_kernel<<<E / 8, 256>>>(q_kn, U, stu_id, kn_id, gamma_c, d, score,
                                 beta2, gs, A_emb);
    init0b_kernel<<<256, 256>>>(beta1, W, user);
    init1_kernel<<<dim3(NBLK, K), 256>>>(Bm);
    for (int step = 0; step < NUM_UPDATE; ++step) {
        big_kernel<<<dim3(NBLK, K), 256>>>(Bm, d, score, gs, A_emb, out, step);
    }
    predict_kernel<<<(M + 255) / 256, 256>>>(d, alpha, gamma_e, ex_id, out);
}

// round 6
// speedup vs baseline: 1.6150x; 1.6150x over previous
#include <cuda_runtime.h>
#include <math.h>

#define K 128
#define E 4096
#define M 512
#define NUM_UPDATE 3
#define THRESHOLD 0.05f
#define HOT 8
#define MAXNZ 32
#define NBLK 8            // e-chunks in big grid
#define EPB 512           // e per block (2 per thread, 256 threads)

// ---------------- device scratch ----------------
__device__ __align__(16) unsigned char g_nzpk[E * MAXNZ];
__device__ unsigned char g_cnt[E];
__device__ float4 g_cc[E];                    // (c0, c1, score, 1/d) per e
__device__ float  g_bz[E];                    // beta2 * Zc
__device__ float2 g_buw[(size_t)K * E];       // (beta1, user*W)
__device__ float  g_Bc[(size_t)K * E * HOT];  // gathered B, diag/pad zeroed
__device__ float  g_u[K];
__device__ int    g_upd[K];
__device__ float  g_partial[K * NBLK];
__device__ unsigned g_done[NUM_UPDATE];

__device__ __forceinline__ float sigm_neg(float x) {
    return __fdividef(1.0f, 1.0f + __expf(x));  // sigmoid(-x)
}

// ---------------- init0: nz lists, per-e constants, u0, upd ----------------
// grid = E/8 = 512 blocks of 256 (warp per e)
__global__ void init0_kernel(const float* __restrict__ q_kn,
                             const float* __restrict__ U,
                             const int* __restrict__ stu_id,
                             const int* __restrict__ kn_id,
                             const float* __restrict__ gamma_c,
                             const float* __restrict__ dd,
                             const float* __restrict__ score,
                             const float* __restrict__ beta2,
                             const float* __restrict__ gs,
                             const float* __restrict__ A_emb) {
    int tid = threadIdx.x;
    int w = tid >> 5, l = tid & 31;
    int e = blockIdx.x * 8 + w;

    int base = 0;
#pragma unroll
    for (int r = 0; r < 4; r++) {
        int j = r * 32 + l;
        float q = q_kn[(size_t)e * K + j];
        unsigned m = __ballot_sync(0xFFFFFFFFu, q != 0.0f);
        if (q != 0.0f) {
            int pos = base + __popc(m & ((1u << l) - 1u));
            if (pos < MAXNZ) g_nzpk[e * MAXNZ + pos] = (unsigned char)j;
        }
        base += __popc(m);
    }
    if (l == 0) {
        g_cnt[e] = (unsigned char)(base < MAXNZ ? base : MAXNZ);
        float invd = 1.0f / dd[e];
        float sc   = score[e];
        float x  = (gamma_c[e] * invd) * (sc - 0.5f);
        g_bz[e]  = beta2[e] * (sigm_neg(x) - 0.5f);
        float c0 = A_emb[3 * e + 0] * (1.0f - gs[2 * e + 0])
                 + A_emb[3 * e + 1] * (1.0f - gs[2 * e + 1]);
        float c1 = A_emb[3 * e + 2];
        g_cc[e] = make_float4(c0, c1, sc, invd);
    }

    if (blockIdx.x == 0) {
        if (tid < NUM_UPDATE) g_done[tid] = 0u;
        if (tid < K) {
            g_u[tid] = U[(size_t)stu_id[0] * K + tid];
            g_upd[tid] = 0;
        }
        __syncthreads();
        if (tid < K) {
            int kn = kn_id[tid];
            if (kn >= 0 && kn < K) g_upd[kn] = 1;
        }
    }
}

// ---------------- init0b: buw = (beta1, user*W), vectorized ----------------
__global__ void init0b_kernel(const float* __restrict__ beta1,
                              const float* __restrict__ W,
                              const float* __restrict__ user) {
    int i4 = blockIdx.x * blockDim.x + threadIdx.x;   // float4 index
    const int N4 = K * E / 4;
    for (; i4 < N4; i4 += gridDim.x * blockDim.x) {
        float4 b = ((const float4*)beta1)[i4];
        float4 w = ((const float4*)W)[i4];
        float4 u = ((const float4*)user)[i4];
        float2* dst = g_buw + i4 * 4;
        dst[0] = make_float2(b.x, u.x * w.x);
        dst[1] = make_float2(b.y, u.y * w.y);
        dst[2] = make_float2(b.z, u.z * w.z);
        dst[3] = make_float2(b.w, u.w * w.w);
    }
}

// ---------------- init1: build Bc (one-time scattered gather, batched) ----------------
// grid = (NBLK, K), 256 threads, 2 e's per thread
__global__ __launch_bounds__(256, 2) void init1_kernel(const float* __restrict__ Bm) {
    int k = blockIdx.y;
    size_t kE = (size_t)k * E;
    int tid = threadIdx.x;
    int e0 = blockIdx.x * EPB + tid;

    uint2 pk[2]; int cnt[2];
#pragma unroll
    for (int r = 0; r < 2; r++) {
        int e = e0 + r * 256;
        pk[r]  = *(const uint2*)(g_nzpk + e * MAXNZ);
        cnt[r] = g_cnt[e];
    }
    float v[2][HOT];
#pragma unroll
    for (int r = 0; r < 2; r++) {
        int e = e0 + r * 256;
        const float* __restrict__ Brow = Bm + (kE + e) * K;
        unsigned pw0 = pk[r].x, pw1 = pk[r].y;
#pragma unroll
        for (int i = 0; i < HOT; i++) {
            int j = ((i < 4 ? pw0 : pw1) >> ((i & 3) * 8)) & 0xFF;
            v[r][i] = (i < cnt[r] && j != k) ? __ldg(Brow + j) : 0.0f;
        }
    }
#pragma unroll
    for (int r = 0; r < 2; r++) {
        int e = e0 + r * 256;
        float4* dst = (float4*)(g_Bc + (kE + e) * HOT);
        dst[0] = make_float4(v[r][0], v[r][1], v[r][2], v[r][3]);
        dst[1] = make_float4(v[r][4], v[r][5], v[r][6], v[r][7]);
    }
}

// ---------------- big step kernel: inline dval/Ic from smem, tiny epilogue ----------------
// grid = (NBLK, K) = 1024 blocks of 256; 2 e's per thread
__global__ __launch_bounds__(256) void big_kernel(const float* __restrict__ Bm,
                                                  float* __restrict__ out,
                                                  int step) {
    int k = blockIdx.y;
    size_t kE = (size_t)k * E;
    int tid = threadIdx.x;

    __shared__ float2 s_ud[K];   // (u, dv)
    if (tid < K) {
        float u = g_u[tid];
        float dv = u - 0.5f;
        dv = (fabsf(dv) > THRESHOLD) ? dv : 0.0f;
        s_ud[tid] = make_float2(u, dv);
    }
    __syncthreads();

    float acc = 0.0f;
#pragma unroll
    for (int r = 0; r < 2; r++) {
        int e = blockIdx.x * EPB + r * 256 + tid;
        uint2 pk   = *(const uint2*)(g_nzpk + e * MAXNZ);
        int cnt    = g_cnt[e];
        const float4* bc = (const float4*)(g_Bc + (kE + e) * HOT);
        float4 b0 = bc[0], b1 = bc[1];
        float4 cc  = g_cc[e];
        float  bz  = g_bz[e];
        float2 bw  = g_buw[kE + e];

        float bcv[HOT] = {b0.x, b0.y, b0.z, b0.w, b1.x, b1.y, b1.z, b1.w};
        float su = 0.0f, dot = 0.0f;
        unsigned pw0 = pk.x, pw1 = pk.y;
#pragma unroll
        for (int i = 0; i < HOT; i++) {
            int j = ((i < 4 ? pw0 : pw1) >> ((i & 3) * 8)) & 0xFF;
            float2 ud = s_ud[j];
            su  += (i < cnt) ? ud.x : 0.0f;
            dot += bcv[i] * ud.y;            // bcv already 0 for pad/diag
        }
        if (cnt > HOT) {                      // rare tail
            const uint4* pkp = (const uint4*)(g_nzpk + e * MAXNZ);
            uint4 p0 = pkp[0], p1 = pkp[1];
            unsigned pw[8] = {p0.x, p0.y, p0.z, p0.w, p1.x, p1.y, p1.z, p1.w};
            const float* __restrict__ Brow = Bm + (kE + e) * K;
            for (int i = HOT; i < cnt; i++) {
                int j = (pw[i >> 2] >> ((i & 3) * 8)) & 0xFF;
                float2 ud = s_ud[j];
                su += ud.x;
                if (j != k) dot += __ldg(Brow + j) * ud.y;
            }
        }
        // Ic inline:  yc = exp(-(sc - su/d)^2);  ic = c0 + c1*yc;  Ic = sigm(-ic)
        float t  = cc.z - su * cc.w;
        float ic = cc.x + cc.y * __expf(-t * t);
        float Ic = sigm_neg(ic);
        float gkc = sigm_neg(dot) - 1.0f;
        float wk  = Ic * (bw.x * gkc + bz);
        acc += bw.y * wk;
    }

    // deterministic block reduction
    __shared__ float warpacc[8];
    int w = tid >> 5, l = tid & 31;
    acc += __shfl_xor_sync(0xFFFFFFFFu, acc, 16);
    acc += __shfl_xor_sync(0xFFFFFFFFu, acc, 8);
    acc += __shfl_xor_sync(0xFFFFFFFFu, acc, 4);
    acc += __shfl_xor_sync(0xFFFFFFFFu, acc, 2);
    acc += __shfl_xor_sync(0xFFFFFFFFu, acc, 1);
    if (l == 0) warpacc[w] = acc;
    __syncthreads();

    __shared__ bool is_last;
    if (tid == 0) {
        float s = 0.0f;
#pragma unroll
        for (int i = 0; i < 8; i++) s += warpacc[i];
        g_partial[k * NBLK + blockIdx.x] = s;
        __threadfence();
        unsigned t = atomicAdd(&g_done[step], 1u);
        is_last = (t == (unsigned)(NBLK * K - 1));
    }
    __syncthreads();
    if (!is_last) return;
    __threadfence();

    // ---- tiny fused epilogue (one block): u update + diff norm + outputs ----
    __shared__ float red[K];
    if (tid < K) {
        float s = 0.0f;
#pragma unroll
        for (int c = 0; c < NBLK; c++) s += g_partial[tid * NBLK + c];
        float u_old = g_u[tid];
        float u_new = sigm_neg(s);
        float un = g_upd[tid] ? u_new : u_old;
        float ddf = un - u_old;
        red[tid] = ddf * ddf;
        g_u[tid] = un;
        if (step == NUM_UPDATE - 2) out[K + tid] = un;  // state_2nd_last
        if (step == NUM_UPDATE - 1) out[tid]     = un;  // state_last
    }
    __syncthreads();
#pragma unroll
    for (int off = 64; off > 0; off >>= 1) {
        if (tid < off && tid + off < K) red[tid] += red[tid + off];
        __syncthreads();
    }
    if (tid == 0) out[2 * K + M + step] = sqrtf(red[0]);
}

// ---------------- final predict ----------------
__global__ void predict_kernel(const float* __restrict__ dd,
                               const float* __restrict__ alpha,
                               const float* __restrict__ gamma_e,
                               const int* __restrict__ ex_id,
                               float* __restrict__ out) {
    __shared__ float s_u[K];
    int tid = threadIdx.x;
    if (tid < K) s_u[tid] = g_u[tid];
    __syncthreads();

    int m = blockIdx.x * 256 + tid;
    if (m < M) {
        int e = ex_id[m];
        const uint4* pkp = (const uint4*)(g_nzpk + e * MAXNZ);
        uint4 p0 = pkp[0], p1 = pkp[1];
        unsigned pw[8] = {p0.x, p0.y, p0.z, p0.w, p1.x, p1.y, p1.z, p1.w};
        int cnt = g_cnt[e];
        float accv = 0.0f;
        for (int i = 0; i < cnt; i++) {
            int j = (pw[i >> 2] >> ((i & 3) * 8)) & 0xFF;
            accv += s_u[j];
        }
        float Ukse = accv / dd[e] - 0.5f;
        out[2 * K + m] = sigm_neg(alpha[e] * Ukse + gamma_e[e]);
    }
}

// ---------------- launch ----------------
extern "C" void kernel_launch(void* const* d_in, const int* in_sizes, int n_in,
                              void* d_out, int out_size) {
    const float* U       = (const float*)d_in[0];
    const float* W       = (const float*)d_in[1];
    const float* beta1   = (const float*)d_in[2];
    const float* beta2   = (const float*)d_in[3];
    const float* Bm      = (const float*)d_in[4];
    const float* gs      = (const float*)d_in[5];
    const float* A_emb   = (const float*)d_in[6];
    const float* gamma_c = (const float*)d_in[7];
    const float* gamma_e = (const float*)d_in[8];
    const float* alpha   = (const float*)d_in[9];
    const float* score   = (const float*)d_in[10];
    const float* user    = (const float*)d_in[11];
    const float* q_kn    = (const float*)d_in[12];
    const float* d       = (const float*)d_in[13];
    const int*   stu_id  = (const int*)d_in[14];
    const int*   kn_id   = (const int*)d_in[15];
    const int*   ex_id   = (const int*)d_in[16];
    float* out = (float*)d_out;

    init0_kernel<<<E / 8, 256>>>(q_kn, U, stu_id, kn_id, gamma_c, d, score,
                                 beta2, gs, A_emb);
    init0b_kernel<<<256, 256>>>(beta1, W, user);
    init1_kernel<<<dim3(NBLK, K), 256>>>(Bm);
    for (int step = 0; step < NUM_UPDATE; ++step) {
        big_kernel<<<dim3(NBLK, K), 256>>>(Bm, out, step);
    }
    predict_kernel<<<(M + 255) / 256, 256>>>(d, alpha, gamma_e, ex_id, out);
}